// round 16
// baseline (speedup 1.0000x reference)
#include <cuda_runtime.h>
#include <cuda_fp16.h>
#include <cstdint>

// ---------------------------------------------------------------------------
// GraphSAGE (3x SAGEConv + BN/ReLU) on B200 / sm_100a.
// R15 design (best: 383.0us) + launch-graph compression:
//   - fp16 end-to-end GEMM datapath (m16n8k16, fp32 accumulate), fp32 h1/h2.
//   - BN column stats fused into the GEMM epilogue.
//   - CSR scan: single-pass decoupled lookback (replaces 3-kernel chain);
//     flags/ticket self-resetting (scatter block 0 restores the invariant).
//   - hist fused into the prologue kernel (blockIdx-partitioned).
//   - Layer-2: single fused N=128 GEMM over [Wl2|Wr2]^T; split epilogue.
// ---------------------------------------------------------------------------

#define NNODES 50000
#define NEDGES 1600000
#define INDIM  128
#define HIDDIM 256
#define OUTDIM 64
#define NBY    ((NNODES + 127) / 128)
#define NBLK   ((NNODES + 255) / 256)        // 196 scan blocks
#define WSEG   229376                        // weight-prep elements
#define XSEG   (NNODES * INDIM / 4)          // x float4 elements
#define HB     ((NEDGES + 255) / 256)        // hist blocks in fused kernel

// ------------------------- scratch (device globals) ------------------------
__device__ float g_h1 [(size_t)NNODES * HIDDIM];
__device__ float g_h2 [(size_t)NNODES * HIDDIM];
__device__ __align__(16) __half g_aggh[(size_t)NNODES * HIDDIM];
__device__ __align__(16) __half g_xh  [(size_t)NNODES * INDIM];
__device__ __align__(16) __half g_h1h [(size_t)NNODES * HIDDIM];
__device__ __align__(16) __half g_h2h [(size_t)NNODES * HIDDIM];
__device__ __align__(16) __half g_yh  [(size_t)NNODES * OUTDIM];
__device__ __align__(16) __half g_wl0t[HIDDIM * INDIM];
__device__ __align__(16) __half g_wr0t[HIDDIM * INDIM];
__device__ __align__(16) __half g_wl1t[HIDDIM * HIDDIM];
__device__ __align__(16) __half g_wr1t[HIDDIM * HIDDIM];
__device__ __align__(16) __half g_wcatt[128 * HIDDIM];
__device__ float g_invdeg[NNODES];
__device__ int   g_cnt[NNODES];              // BSS zero; re-zeroed by scan
__device__ int   g_rowptr[NNODES + 1];
__device__ int   g_fill[NNODES];
__device__ int   g_csr[NEDGES];
__device__ int   g_ticket;                   // BSS zero; reset by scatter
__device__ unsigned long long g_flag[NBLK];  // BSS zero; reset by scatter
__device__ float g_ps[(size_t)NBY * HIDDIM];
__device__ float g_pq[(size_t)NBY * HIDDIM];
__device__ __align__(16) float g_scale[HIDDIM];
__device__ __align__(16) float g_shift[HIDDIM];

// ------------------------------ cp.async utils ------------------------------
__device__ __forceinline__ void cp_async16(uint32_t saddr, const void* gptr, bool pred) {
    int sz = pred ? 16 : 0;
    asm volatile("cp.async.cg.shared.global [%0], [%1], 16, %2;\n"
                 :: "r"(saddr), "l"(gptr), "r"(sz));
}
__device__ __forceinline__ void cp_commit() {
    asm volatile("cp.async.commit_group;\n" ::: "memory");
}
__device__ __forceinline__ void cp_wait0() {
    asm volatile("cp.async.wait_group 0;\n" ::: "memory");
}

// ------------------- fused hist + prologue (independent work) ----------------
__global__ void hist_prologue_kernel(const int* __restrict__ ei, int* __restrict__ cnt,
                                     const float* __restrict__ Wl0, const float* __restrict__ Wr0,
                                     const float* __restrict__ Wl1, const float* __restrict__ Wr1,
                                     const float* __restrict__ Wl2, const float* __restrict__ Wr2,
                                     __half* __restrict__ wl0t, __half* __restrict__ wr0t,
                                     __half* __restrict__ wl1t, __half* __restrict__ wr1t,
                                     __half* __restrict__ wcatt,
                                     const float4* __restrict__ x4, __half2* __restrict__ xh2) {
    if (blockIdx.x < HB) {
        int e = blockIdx.x * 256 + threadIdx.x;
        if (e < NEDGES) {
            int d = ei[NEDGES + e];
            if ((unsigned)d < (unsigned)NNODES)
                atomicAdd(&cnt[d], 1);
        }
        return;
    }
    int i = (blockIdx.x - HB) * 256 + threadIdx.x;
    if (i < WSEG) {
        if (i < 65536) {
            int j = i & 32767;
            int n = j >> 7, k = j & 127;
            const float* W = (i < 32768) ? Wl0 : Wr0;
            __half* Wt = (i < 32768) ? wl0t : wr0t;
            Wt[j] = __float2half_rn(W[k * HIDDIM + n]);
        } else if (i < 196608) {
            int j = (i - 65536) & 65535;
            int n = j >> 8, k = j & 255;
            const float* W = (i < 131072) ? Wl1 : Wr1;
            __half* Wt = (i < 131072) ? wl1t : wr1t;
            Wt[j] = __float2half_rn(W[k * HIDDIM + n]);
        } else {
            int j = i - 196608;
            int n = j >> 8, k = j & 255;
            float v = (n < 64) ? Wl2[k * 64 + n] : Wr2[k * 64 + (n - 64)];
            wcatt[j] = __float2half_rn(v);
        }
    } else {
        int j = i - WSEG;
        if (j < XSEG) {
            float4 v = x4[j];
            xh2[j * 2 + 0] = __floats2half2_rn(v.x, v.y);
            xh2[j * 2 + 1] = __floats2half2_rn(v.z, v.w);
        }
    }
}

// ---------- single-pass scan (decoupled lookback) + prep + cnt reset ---------
__global__ void scan_prep_kernel(int* __restrict__ cnt, int* __restrict__ rowptr,
                                 int* __restrict__ fill, float* __restrict__ invdeg, int n) {
    __shared__ int wsum[8];
    __shared__ int sbid;
    __shared__ int sexcl;
    if (threadIdx.x == 0) sbid = atomicAdd(&g_ticket, 1);
    __syncthreads();
    int bid = sbid;
    int i = bid * 256 + threadIdx.x;
    int lane = threadIdx.x & 31, wid = threadIdx.x >> 5;
    int v = (i < n) ? cnt[i] : 0;
    int s = v;
#pragma unroll
    for (int off = 1; off < 32; off <<= 1) {
        int u = __shfl_up_sync(0xffffffffu, s, off);
        if (lane >= off) s += u;
    }
    if (lane == 31) wsum[wid] = s;
    __syncthreads();
    if (wid == 0 && lane < 8) {
        int w = wsum[lane];
#pragma unroll
        for (int off = 1; off < 8; off <<= 1) {
            int u = __shfl_up_sync(0xffu, w, off);
            if (lane >= off) w += u;
        }
        wsum[lane] = w;
    }
    __syncthreads();
    int sIncl = s + (wid ? wsum[wid - 1] : 0);
    int T = wsum[7];                          // block total

    if (threadIdx.x == 0) {
        if (bid == 0) {
            atomicExch(&g_flag[0], (2ULL << 32) | (unsigned)T);
            sexcl = 0;
        } else {
            atomicExch(&g_flag[bid], (1ULL << 32) | (unsigned)T);
            int running = 0;
            int j = bid - 1;
            while (true) {
                unsigned long long f;
                do { f = atomicAdd(&g_flag[j], 0ULL); } while ((f >> 32) == 0ULL);
                running += (int)(unsigned)f;
                if ((f >> 32) == 2ULL) break;
                j--;
            }
            sexcl = running;
            atomicExch(&g_flag[bid], (2ULL << 32) | (unsigned)(running + T));
        }
    }
    __syncthreads();
    int incl = sIncl + sexcl;
    if (i < n) {
        rowptr[i + 1] = incl;
        fill[i] = incl - v;
        invdeg[i] = 1.0f / (float)(v > 0 ? v : 1);
        cnt[i] = 0;                           // restore invariant
    }
    if (i == 0) rowptr[0] = 0;
}

// ----------------- scatter (+ resets scan ticket/flags) ----------------------
__global__ void scatter_kernel(const int* __restrict__ ei, int ne,
                               int* __restrict__ fill, int* __restrict__ csr) {
    if (blockIdx.x == 0) {
        if (threadIdx.x == 0) g_ticket = 0;
        if (threadIdx.x < NBLK) g_flag[threadIdx.x] = 0ULL;   // NBLK <= 256
    }
    int e = blockIdx.x * blockDim.x + threadIdx.x;
    if (e < ne) {
        int s = ei[e];
        int d = ei[ne + e];
        if ((unsigned)d < (unsigned)NNODES && (unsigned)s < (unsigned)NNODES) {
            int pos = atomicAdd(&fill[d], 1);
            if ((unsigned)pos < (unsigned)NEDGES)
                csr[pos] = s;
        }
    }
}

// ------------------ act (BN+ReLU) -> fp16 (gather + GEMM A) ------------------
__global__ void act_f16_kernel(const float4* __restrict__ H, __half2* __restrict__ O2,
                               int n4, const float* __restrict__ sc, const float* __restrict__ sh) {
    int i = blockIdx.x * blockDim.x + threadIdx.x;
    if (i >= n4) return;
    int c = (i * 4) & (HIDDIM - 1);
    float4 v = H[i];
    v.x = fmaxf(v.x * __ldg(sc + c + 0) + __ldg(sh + c + 0), 0.f);
    v.y = fmaxf(v.y * __ldg(sc + c + 1) + __ldg(sh + c + 1), 0.f);
    v.z = fmaxf(v.z * __ldg(sc + c + 2) + __ldg(sh + c + 2), 0.f);
    v.w = fmaxf(v.w * __ldg(sc + c + 3) + __ldg(sh + c + 3), 0.f);
    O2[i * 2 + 0] = __floats2half2_rn(v.x, v.y);
    O2[i * 2 + 1] = __floats2half2_rn(v.z, v.w);
}

// ------------------------- fp16 aggregation (D=256) --------------------------
__global__ void agg256_f16_kernel(const __half* __restrict__ Xh, __half* __restrict__ Out,
                                  const int* __restrict__ rowptr, const int* __restrict__ csr,
                                  const float* __restrict__ invdeg, int n_nodes) {
    int node = (blockIdx.x * blockDim.x + threadIdx.x) >> 5;
    if (node >= n_nodes) return;
    int lane = threadIdx.x & 31;
    int doff = lane * 8;

    float acc0[8], acc1[8];
#pragma unroll
    for (int i = 0; i < 8; i++) { acc0[i] = 0.f; acc1[i] = 0.f; }

    int beg = rowptr[node];
    int end = rowptr[node + 1];
    int e = beg;

    auto accum = [&](uint4 u, float* acc) {
        float2 f0 = __half22float2(*reinterpret_cast<__half2*>(&u.x));
        float2 f1 = __half22float2(*reinterpret_cast<__half2*>(&u.y));
        float2 f2 = __half22float2(*reinterpret_cast<__half2*>(&u.z));
        float2 f3 = __half22float2(*reinterpret_cast<__half2*>(&u.w));
        acc[0] += f0.x; acc[1] += f0.y;
        acc[2] += f1.x; acc[3] += f1.y;
        acc[4] += f2.x; acc[5] += f2.y;
        acc[6] += f3.x; acc[7] += f3.y;
    };

    for (; e + 3 < end; e += 4) {
        int s0 = __ldg(csr + e);
        int s1 = __ldg(csr + e + 1);
        int s2 = __ldg(csr + e + 2);
        int s3 = __ldg(csr + e + 3);
        uint4 u0 = __ldg(reinterpret_cast<const uint4*>(Xh + (size_t)s0 * HIDDIM + doff));
        uint4 u1 = __ldg(reinterpret_cast<const uint4*>(Xh + (size_t)s1 * HIDDIM + doff));
        uint4 u2 = __ldg(reinterpret_cast<const uint4*>(Xh + (size_t)s2 * HIDDIM + doff));
        uint4 u3 = __ldg(reinterpret_cast<const uint4*>(Xh + (size_t)s3 * HIDDIM + doff));
        accum(u0, acc0); accum(u1, acc1); accum(u2, acc0); accum(u3, acc1);
    }
    for (; e < end; e++) {
        int s0 = __ldg(csr + e);
        uint4 u0 = __ldg(reinterpret_cast<const uint4*>(Xh + (size_t)s0 * HIDDIM + doff));
        accum(u0, acc0);
    }

    float w = __ldg(invdeg + node);
    uint4 ov;
    __half2 h0 = __floats2half2_rn((acc0[0] + acc1[0]) * w, (acc0[1] + acc1[1]) * w);
    __half2 h1v = __floats2half2_rn((acc0[2] + acc1[2]) * w, (acc0[3] + acc1[3]) * w);
    __half2 h2v = __floats2half2_rn((acc0[4] + acc1[4]) * w, (acc0[5] + acc1[5]) * w);
    __half2 h3 = __floats2half2_rn((acc0[6] + acc1[6]) * w, (acc0[7] + acc1[7]) * w);
    ov.x = *reinterpret_cast<uint32_t*>(&h0);
    ov.y = *reinterpret_cast<uint32_t*>(&h1v);
    ov.z = *reinterpret_cast<uint32_t*>(&h2v);
    ov.w = *reinterpret_cast<uint32_t*>(&h3);
    *reinterpret_cast<uint4*>(Out + (size_t)node * HIDDIM + doff) = ov;
}

// ------------------------- fp16 aggregation (D=128) --------------------------
__global__ void agg128_f16_kernel(const __half* __restrict__ Xh, __half* __restrict__ Out,
                                  const int* __restrict__ rowptr, const int* __restrict__ csr,
                                  const float* __restrict__ invdeg, int n_nodes) {
    int node = (blockIdx.x * blockDim.x + threadIdx.x) >> 5;
    if (node >= n_nodes) return;
    int lane = threadIdx.x & 31;
    int doff = lane * 4;

    float acc0[4], acc1[4];
#pragma unroll
    for (int i = 0; i < 4; i++) { acc0[i] = 0.f; acc1[i] = 0.f; }

    int beg = rowptr[node];
    int end = rowptr[node + 1];
    int e = beg;

    auto accum = [&](uint2 u, float* acc) {
        float2 f0 = __half22float2(*reinterpret_cast<__half2*>(&u.x));
        float2 f1 = __half22float2(*reinterpret_cast<__half2*>(&u.y));
        acc[0] += f0.x; acc[1] += f0.y;
        acc[2] += f1.x; acc[3] += f1.y;
    };

    for (; e + 3 < end; e += 4) {
        int s0 = __ldg(csr + e);
        int s1 = __ldg(csr + e + 1);
        int s2 = __ldg(csr + e + 2);
        int s3 = __ldg(csr + e + 3);
        uint2 u0 = __ldg(reinterpret_cast<const uint2*>(Xh + (size_t)s0 * INDIM + doff));
        uint2 u1 = __ldg(reinterpret_cast<const uint2*>(Xh + (size_t)s1 * INDIM + doff));
        uint2 u2 = __ldg(reinterpret_cast<const uint2*>(Xh + (size_t)s2 * INDIM + doff));
        uint2 u3 = __ldg(reinterpret_cast<const uint2*>(Xh + (size_t)s3 * INDIM + doff));
        accum(u0, acc0); accum(u1, acc1); accum(u2, acc0); accum(u3, acc1);
    }
    for (; e < end; e++) {
        int s0 = __ldg(csr + e);
        uint2 u0 = __ldg(reinterpret_cast<const uint2*>(Xh + (size_t)s0 * INDIM + doff));
        accum(u0, acc0);
    }

    float w = __ldg(invdeg + node);
    __half2 h0 = __floats2half2_rn((acc0[0] + acc1[0]) * w, (acc0[1] + acc1[1]) * w);
    __half2 h1v = __floats2half2_rn((acc0[2] + acc1[2]) * w, (acc0[3] + acc1[3]) * w);
    uint2 ov;
    ov.x = *reinterpret_cast<uint32_t*>(&h0);
    ov.y = *reinterpret_cast<uint32_t*>(&h1v);
    *reinterpret_cast<uint2*>(Out + (size_t)node * INDIM + doff) = ov;
}

// ------------------------- fp16 aggregation (D=64, ADD) ----------------------
__global__ void agg64_f16_kernel(const __half* __restrict__ Yh, float* __restrict__ Out,
                                 const int* __restrict__ rowptr, const int* __restrict__ csr,
                                 const float* __restrict__ invdeg, int n_nodes) {
    int node = (blockIdx.x * blockDim.x + threadIdx.x) >> 5;
    if (node >= n_nodes) return;
    int lane = threadIdx.x & 31;
    int doff = lane * 2;

    float a0 = 0.f, a1 = 0.f, b0 = 0.f, b1 = 0.f;

    int beg = rowptr[node];
    int end = rowptr[node + 1];
    int e = beg;

    for (; e + 3 < end; e += 4) {
        int s0 = __ldg(csr + e);
        int s1 = __ldg(csr + e + 1);
        int s2 = __ldg(csr + e + 2);
        int s3 = __ldg(csr + e + 3);
        float2 f0 = __half22float2(*reinterpret_cast<const __half2*>(Yh + (size_t)s0 * OUTDIM + doff));
        float2 f1 = __half22float2(*reinterpret_cast<const __half2*>(Yh + (size_t)s1 * OUTDIM + doff));
        float2 f2 = __half22float2(*reinterpret_cast<const __half2*>(Yh + (size_t)s2 * OUTDIM + doff));
        float2 f3 = __half22float2(*reinterpret_cast<const __half2*>(Yh + (size_t)s3 * OUTDIM + doff));
        a0 += f0.x + f2.x;  b0 += f1.x + f3.x;
        a1 += f0.y + f2.y;  b1 += f1.y + f3.y;
    }
    for (; e < end; e++) {
        int s0 = __ldg(csr + e);
        float2 f0 = __half22float2(*reinterpret_cast<const __half2*>(Yh + (size_t)s0 * OUTDIM + doff));
        a0 += f0.x; a1 += f0.y;
    }

    float w = __ldg(invdeg + node);
    float* o = Out + (size_t)node * OUTDIM + doff;
    o[0] += (a0 + b0) * w;
    o[1] += (a1 + b1) * w;
}

// ------------------------------ FP16 GEMM (R12) ------------------------------
__device__ __forceinline__ void mma_f16(float c[4], const unsigned a[4], const unsigned b[2]) {
    asm volatile(
        "mma.sync.aligned.m16n8k16.row.col.f32.f16.f16.f32 "
        "{%0,%1,%2,%3}, {%4,%5,%6,%7}, {%8,%9}, {%0,%1,%2,%3};"
        : "+f"(c[0]), "+f"(c[1]), "+f"(c[2]), "+f"(c[3])
        : "r"(a[0]), "r"(a[1]), "r"(a[2]), "r"(a[3]), "r"(b[0]), "r"(b[1]));
}

template <int BM, int BN, int WM, int WN>
__global__ void __launch_bounds__(256, 2)
gemm_f16(const __half* __restrict__ A0, const __half* __restrict__ B0t,
         const __half* __restrict__ A1, const __half* __restrict__ B1t,
         float* __restrict__ C, __half* __restrict__ Cy,
         int M, int N, int K, const float* __restrict__ bias,
         float* __restrict__ Sp, float* __restrict__ Sq) {
    constexpr int BK = 32, THREADS = 256;
    constexpr int WCOLS = BN / WN;
    constexpr int MT = WM / 16, NT = WN / 8;
    constexpr int AST = BK + 8;
    constexpr int BST = BK + 8;
    constexpr int ACH = (BM * BK) / (8 * THREADS);
    constexpr int BCH = (BN * BK) / (8 * THREADS);
    constexpr int ABUF = BM * AST;
    constexpr int BBUF = BN * BST;
    static_assert((BM / WM) * (BN / WN) == 8, "8 warps");

    __shared__ __half Asm[2 * ABUF];
    __shared__ __half Bsm[2 * BBUF];
    __shared__ float sstat[2][2][BN];

    int tid = threadIdx.x, lane = tid & 31, warp = tid >> 5;
    int wrow = warp / WCOLS, wcol = warp % WCOLS;
    int block_m = blockIdx.y * BM, block_n = blockIdx.x * BN;
    int g = lane >> 2, q = lane & 3;

    uint32_t AsmAddr = (uint32_t)__cvta_generic_to_shared(Asm);
    uint32_t BsmAddr = (uint32_t)__cvta_generic_to_shared(Bsm);

    float acc[MT][NT][4];
#pragma unroll
    for (int mt = 0; mt < MT; mt++)
#pragma unroll
        for (int nt = 0; nt < NT; nt++)
#pragma unroll
            for (int r = 0; r < 4; r++) acc[mt][nt][r] = 0.0f;

    const int kiters = K / BK;
    const int npass = A1 ? 2 : 1;
    const int total = npass * kiters;

    auto issue_stage = [&](int it, int buf) {
        int pass = it / kiters;
        int k0 = (it - pass * kiters) * BK;
        const __half* Ap = pass ? A1 : A0;
        const __half* Bp = pass ? B1t : B0t;
#pragma unroll
        for (int i = 0; i < ACH; i++) {
            int chunk = tid + i * THREADS;
            int r = chunk >> 2;
            int c8 = (chunk & 3) << 3;
            int gr = block_m + r;
            uint32_t dst = AsmAddr + (buf * ABUF + r * AST + c8) * 2;
            cp_async16(dst, Ap + (size_t)gr * K + k0 + c8, gr < M);
        }
#pragma unroll
        for (int i = 0; i < BCH; i++) {
            int chunk = tid + i * THREADS;
            int r = chunk >> 2;
            int c8 = (chunk & 3) << 3;
            uint32_t dst = BsmAddr + (buf * BBUF + r * BST + c8) * 2;
            cp_async16(dst, Bp + (size_t)(block_n + r) * K + k0 + c8, true);
        }
        cp_commit();
    };

    issue_stage(0, 0);
    int buf = 0;
    for (int it = 0; it < total; ++it) {
        cp_wait0();
        __syncthreads();
        if (it + 1 < total) issue_stage(it + 1, buf ^ 1);

        const __half* Ab = Asm + buf * ABUF;
        const __half* Bb = Bsm + buf * BBUF;
#pragma unroll
        for (int s = 0; s < BK / 16; ++s) {
            int kb = s * 16 + q * 2;
            unsigned af[MT][4], bf[NT][2];
#pragma unroll
            for (int mt = 0; mt < MT; ++mt) {
                int m = wrow * WM + mt * 16 + g;
                af[mt][0] = *reinterpret_cast<const unsigned*>(Ab + m * AST + kb);
                af[mt][1] = *reinterpret_cast<const unsigned*>(Ab + (m + 8) * AST + kb);
                af[mt][2] = *reinterpret_cast<const unsigned*>(Ab + m * AST + kb + 8);
                af[mt][3] = *reinterpret_cast<const unsigned*>(Ab + (m + 8) * AST + kb + 8);
            }
#pragma unroll
            for (int nt = 0; nt < NT; ++nt) {
                int nn = wcol * WN + nt * 8 + g;
                bf[nt][0] = *reinterpret_cast<const unsigned*>(Bb + nn * BST + kb);
                bf[nt][1] = *reinterpret_cast<const unsigned*>(Bb + nn * BST + kb + 8);
            }
#pragma unroll
            for (int mt = 0; mt < MT; ++mt)
#pragma unroll
                for (int nt = 0; nt < NT; ++nt)
                    mma_f16(acc[mt][nt], af[mt], bf[nt]);
        }
        buf ^= 1;
    }

    float csum[NT][2], csq[NT][2];
#pragma unroll
    for (int nt = 0; nt < NT; nt++) {
        csum[nt][0] = csum[nt][1] = 0.f;
        csq[nt][0]  = csq[nt][1]  = 0.f;
    }

#pragma unroll
    for (int mt = 0; mt < MT; ++mt) {
        int r0 = block_m + wrow * WM + mt * 16 + g;
        int r1 = r0 + 8;
#pragma unroll
        for (int nt = 0; nt < NT; ++nt) {
            int cn = block_n + wcol * WN + nt * 8 + q * 2;
            if (Cy) {
                if (cn < 64) {
                    if (r0 < M)
                        *reinterpret_cast<__half2*>(Cy + (size_t)r0 * 64 + cn) =
                            __floats2half2_rn(acc[mt][nt][0], acc[mt][nt][1]);
                    if (r1 < M)
                        *reinterpret_cast<__half2*>(Cy + (size_t)r1 * 64 + cn) =
                            __floats2half2_rn(acc[mt][nt][2], acc[mt][nt][3]);
                } else {
                    int co = cn - 64;
                    float b0 = __ldg(bias + co), b1 = __ldg(bias + co + 1);
                    if (r0 < M) {
                        float2 t0 = make_float2(acc[mt][nt][0] + b0, acc[mt][nt][1] + b1);
                        *reinterpret_cast<float2*>(C + (size_t)r0 * 64 + co) = t0;
                    }
                    if (r1 < M) {
                        float2 t1 = make_float2(acc[mt][nt][2] + b0, acc[mt][nt][3] + b1);
                        *reinterpret_cast<float2*>(C + (size_t)r1 * 64 + co) = t1;
                    }
                }
            } else {
                float b0 = 0.f, b1 = 0.f;
                if (bias) { b0 = __ldg(bias + cn); b1 = __ldg(bias + cn + 1); }
                if (r0 < M) {
                    float2 t0 = make_float2(acc[mt][nt][0] + b0, acc[mt][nt][1] + b1);
                    *reinterpret_cast<float2*>(C + (size_t)r0 * N + cn) = t0;
                    if (Sp) {
                        csum[nt][0] += t0.x;        csum[nt][1] += t0.y;
                        csq[nt][0]  += t0.x * t0.x; csq[nt][1]  += t0.y * t0.y;
                    }
                }
                if (r1 < M) {
                    float2 t1 = make_float2(acc[mt][nt][2] + b0, acc[mt][nt][3] + b1);
                    *reinterpret_cast<float2*>(C + (size_t)r1 * N + cn) = t1;
                    if (Sp) {
                        csum[nt][0] += t1.x;        csum[nt][1] += t1.y;
                        csq[nt][0]  += t1.x * t1.x; csq[nt][1]  += t1.y * t1.y;
                    }
                }
            }
        }
    }

    if (Sp) {
#pragma unroll
        for (int nt = 0; nt < NT; nt++)
#pragma unroll
            for (int c = 0; c < 2; c++) {
                float s = csum[nt][c], sq = csq[nt][c];
#pragma unroll
                for (int off = 16; off >= 4; off >>= 1) {
                    s  += __shfl_down_sync(0xffffffffu, s,  off);
                    sq += __shfl_down_sync(0xffffffffu, sq, off);
                }
                if (lane < 4) {
                    int col = wcol * WN + nt * 8 + lane * 2 + c;
                    sstat[wrow][0][col] = s;
                    sstat[wrow][1][col] = sq;
                }
            }
        __syncthreads();
        if (tid < BN) {
            size_t o = (size_t)blockIdx.y * N + block_n + tid;
            Sp[o] = sstat[0][0][tid] + sstat[1][0][tid];
            Sq[o] = sstat[0][1][tid] + sstat[1][1][tid];
        }
    }
}

// ------------------------------- BatchNorm ----------------------------------
__global__ void colstats_final(const float* __restrict__ ps, const float* __restrict__ pq,
                               int nb, float inv_m,
                               const float* __restrict__ g, const float* __restrict__ be,
                               float* __restrict__ scale, float* __restrict__ shift) {
    int c = threadIdx.x;
    float s = 0.f, q = 0.f;
    for (int b = 0; b < nb; b++) {
        s += ps[b * HIDDIM + c];
        q += pq[b * HIDDIM + c];
    }
    float mu  = s * inv_m;
    float var = q * inv_m - mu * mu;
    float rs  = rsqrtf(var + 1e-5f);
    float sc  = g[c] * rs;
    scale[c] = sc;
    shift[c] = be[c] - mu * sc;
}

// --------------------------------- launch -----------------------------------
extern "C" void kernel_launch(void* const* d_in, const int* in_sizes, int n_in,
                              void* d_out, int out_size) {
    const float* x   = (const float*)d_in[0];
    const int*   ei  = (const int*)d_in[1];
    const float* Wl0 = (const float*)d_in[2];
    const float* bl0 = (const float*)d_in[3];
    const float* Wr0 = (const float*)d_in[4];
    const float* Wl1 = (const float*)d_in[5];
    const float* bl1 = (const float*)d_in[6];
    const float* Wr1 = (const float*)d_in[7];
    const float* Wl2 = (const float*)d_in[8];
    const float* bl2 = (const float*)d_in[9];
    const float* Wr2 = (const float*)d_in[10];
    const float* g0  = (const float*)d_in[11];
    const float* be0 = (const float*)d_in[12];
    const float* g1  = (const float*)d_in[13];
    const float* be1 = (const float*)d_in[14];
    float* out = (float*)d_out;

    const int N  = NNODES;
    const int NE = NEDGES;

    float *h1, *h2, *invdeg, *ps, *pq, *scale, *shift;
    __half *aggh, *xh, *h1h, *h2h, *yh, *wl0t, *wr0t, *wl1t, *wr1t, *wcatt;
    int *cnt, *rowptr, *fill, *csr;
    cudaGetSymbolAddress((void**)&h1,     g_h1);
    cudaGetSymbolAddress((void**)&h2,     g_h2);
    cudaGetSymbolAddress((void**)&aggh,   g_aggh);
    cudaGetSymbolAddress((void**)&xh,     g_xh);
    cudaGetSymbolAddress((void**)&h1h,    g_h1h);
    cudaGetSymbolAddress((void**)&h2h,    g_h2h);
    cudaGetSymbolAddress((void**)&yh,     g_yh);
    cudaGetSymbolAddress((void**)&wl0t,   g_wl0t);
    cudaGetSymbolAddress((void**)&wr0t,   g_wr0t);
    cudaGetSymbolAddress((void**)&wl1t,   g_wl1t);
    cudaGetSymbolAddress((void**)&wr1t,   g_wr1t);
    cudaGetSymbolAddress((void**)&wcatt,  g_wcatt);
    cudaGetSymbolAddress((void**)&invdeg, g_invdeg);
    cudaGetSymbolAddress((void**)&cnt,    g_cnt);
    cudaGetSymbolAddress((void**)&rowptr, g_rowptr);
    cudaGetSymbolAddress((void**)&fill,   g_fill);
    cudaGetSymbolAddress((void**)&csr,    g_csr);
    cudaGetSymbolAddress((void**)&ps,     g_ps);
    cudaGetSymbolAddress((void**)&pq,     g_pq);
    cudaGetSymbolAddress((void**)&scale,  g_scale);
    cudaGetSymbolAddress((void**)&shift,  g_shift);

    dim3 gridBig(HIDDIM / 128, (N + 127) / 128);
    dim3 gridL2(1, (N + 127) / 128);
    const int AGG_BLOCKS = (N + 7) / 8;
    const int PRO_BLOCKS = HB + (WSEG + XSEG + 255) / 256;

    // ---- fused hist+prologue, single-pass scan, scatter(+flag reset) ----
    hist_prologue_kernel<<<PRO_BLOCKS, 256>>>(ei, cnt,
                                              Wl0, Wr0, Wl1, Wr1, Wl2, Wr2,
                                              wl0t, wr0t, wl1t, wr1t, wcatt,
                                              (const float4*)x, (__half2*)xh);
    scan_prep_kernel<<<NBLK, 256>>>(cnt, rowptr, fill, invdeg, N);
    scatter_kernel<<<(NE + 255) / 256, 256>>>(ei, NE, fill, csr);

    // ---- Layer 0: h1 = mean_agg(x) @ Wl0 + x @ Wr0 + bl0  (+ fused stats) ----
    agg128_f16_kernel<<<AGG_BLOCKS, 256>>>(xh, aggh, rowptr, csr, invdeg, N);
    gemm_f16<128, 128, 64, 32><<<gridBig, 256>>>(
        aggh, wl0t, xh, wr0t, h1, nullptr, N, HIDDIM, INDIM, bl0, ps, pq);
    colstats_final<<<1, HIDDIM>>>(ps, pq, NBY, 1.0f / (float)N, g0, be0, scale, shift);

    // ---- Layer 1: h2 = mean_agg(act0(h1)) @ Wl1 + act0(h1) @ Wr1 + bl1 ----
    act_f16_kernel<<<(N * HIDDIM / 4 + 255) / 256, 256>>>(
        (const float4*)h1, (__half2*)h1h, N * HIDDIM / 4, scale, shift);
    agg256_f16_kernel<<<AGG_BLOCKS, 256>>>(h1h, aggh, rowptr, csr, invdeg, N);
    gemm_f16<128, 128, 64, 32><<<gridBig, 256>>>(
        aggh, wl1t, h1h, wr1t, h2, nullptr, N, HIDDIM, HIDDIM, bl1, ps, pq);
    colstats_final<<<1, HIDDIM>>>(ps, pq, NBY, 1.0f / (float)N, g1, be1, scale, shift);

    // ---- Layer 2 (fused): [y | out] = act1(h2) @ [Wl2 | Wr2]; y fp16 ----
    act_f16_kernel<<<(N * HIDDIM / 4 + 255) / 256, 256>>>(
        (const float4*)h2, (__half2*)h2h, N * HIDDIM / 4, scale, shift);
    gemm_f16<128, 128, 64, 32><<<gridL2, 256>>>(
        h2h, wcatt, nullptr, nullptr, out, yh, N, 128, HIDDIM, bl2, nullptr, nullptr);
    agg64_f16_kernel<<<AGG_BLOCKS, 256>>>(yh, out, rowptr, csr, invdeg, N);
}

// round 17
// speedup vs baseline: 1.0174x; 1.0174x over previous
#include <cuda_runtime.h>
#include <cuda_fp16.h>
#include <cstdint>

// ---------------------------------------------------------------------------
// GraphSAGE (3x SAGEConv + BN/ReLU) on B200 / sm_100a.
// R15 design (best: 383.0us) + 8-edge-deep agg pipeline (MLP 8):
//   - fp16 end-to-end GEMM datapath (m16n8k16, fp32 accumulate), fp32 h1/h2.
//   - BN column stats fused into the GEMM epilogue.
//   - 3-phase parallel CSR scan (R16's lookback scan regressed; reverted).
//   - cnt[] self-zeroing in scan_final; single fused prologue kernel.
//   - agg256/agg128: 8-edge main loop, bank assignment identical to R15
//     (bit-identical summation order), 4-edge + scalar tails.
//   - Layer-2: single fused N=128 GEMM over [Wl2|Wr2]^T; split epilogue.
// ---------------------------------------------------------------------------

#define NNODES 50000
#define NEDGES 1600000
#define INDIM  128
#define HIDDIM 256
#define OUTDIM 64
#define NBY    ((NNODES + 127) / 128)
#define NBLK   ((NNODES + 255) / 256)
#define WSEG   229376                       // weight-prep elements
#define XSEG   (NNODES * INDIM / 4)         // x float4 elements

// ------------------------- scratch (device globals) ------------------------
__device__ float g_h1 [(size_t)NNODES * HIDDIM];
__device__ float g_h2 [(size_t)NNODES * HIDDIM];
__device__ __align__(16) __half g_aggh[(size_t)NNODES * HIDDIM];
__device__ __align__(16) __half g_xh  [(size_t)NNODES * INDIM];
__device__ __align__(16) __half g_h1h [(size_t)NNODES * HIDDIM];
__device__ __align__(16) __half g_h2h [(size_t)NNODES * HIDDIM];
__device__ __align__(16) __half g_yh  [(size_t)NNODES * OUTDIM];
__device__ __align__(16) __half g_wl0t[HIDDIM * INDIM];
__device__ __align__(16) __half g_wr0t[HIDDIM * INDIM];
__device__ __align__(16) __half g_wl1t[HIDDIM * HIDDIM];
__device__ __align__(16) __half g_wr1t[HIDDIM * HIDDIM];
__device__ __align__(16) __half g_wcatt[128 * HIDDIM];
__device__ float g_invdeg[NNODES];
__device__ int   g_cnt[NNODES];             // BSS zero; re-zeroed by scan_final
__device__ int   g_rowptr[NNODES + 1];
__device__ int   g_fill[NNODES];
__device__ int   g_csr[NEDGES];
__device__ int   g_bsum[NBLK];
__device__ float g_ps[(size_t)NBY * HIDDIM];
__device__ float g_pq[(size_t)NBY * HIDDIM];
__device__ __align__(16) float g_scale[HIDDIM];
__device__ __align__(16) float g_shift[HIDDIM];

// ------------------------------ cp.async utils ------------------------------
__device__ __forceinline__ void cp_async16(uint32_t saddr, const void* gptr, bool pred) {
    int sz = pred ? 16 : 0;
    asm volatile("cp.async.cg.shared.global [%0], [%1], 16, %2;\n"
                 :: "r"(saddr), "l"(gptr), "r"(sz));
}
__device__ __forceinline__ void cp_commit() {
    asm volatile("cp.async.commit_group;\n" ::: "memory");
}
__device__ __forceinline__ void cp_wait0() {
    asm volatile("cp.async.wait_group 0;\n" ::: "memory");
}

// ------------------------------- CSR build ---------------------------------
__global__ void hist_kernel(const int* __restrict__ ei, int ne, int* __restrict__ cnt) {
    int e = blockIdx.x * blockDim.x + threadIdx.x;
    if (e < ne) {
        int d = ei[ne + e];
        if ((unsigned)d < (unsigned)NNODES)
            atomicAdd(&cnt[d], 1);
    }
}

__global__ void scan_bsums_kernel(const int* __restrict__ cnt, int* __restrict__ bsum, int n) {
    __shared__ int sh[256];
    int i = blockIdx.x * 256 + threadIdx.x;
    sh[threadIdx.x] = (i < n) ? cnt[i] : 0;
    __syncthreads();
    for (int s = 128; s > 0; s >>= 1) {
        if (threadIdx.x < s) sh[threadIdx.x] += sh[threadIdx.x + s];
        __syncthreads();
    }
    if (threadIdx.x == 0) bsum[blockIdx.x] = sh[0];
}

__global__ void scan_offsets_kernel(int* __restrict__ bsum, int nb) {
    __shared__ int wsum[8];
    int t = threadIdx.x, lane = t & 31, wid = t >> 5;
    int v = (t < nb) ? bsum[t] : 0;
    int s = v;
#pragma unroll
    for (int off = 1; off < 32; off <<= 1) {
        int u = __shfl_up_sync(0xffffffffu, s, off);
        if (lane >= off) s += u;
    }
    if (lane == 31) wsum[wid] = s;
    __syncthreads();
    if (wid == 0 && lane < 8) {
        int w = wsum[lane];
#pragma unroll
        for (int off = 1; off < 8; off <<= 1) {
            int u = __shfl_up_sync(0xffu, w, off);
            if (lane >= off) w += u;
        }
        wsum[lane] = w;
    }
    __syncthreads();
    int incl = s + (wid ? wsum[wid - 1] : 0);
    if (t < nb) bsum[t] = incl - v;
}

__global__ void scan_final_kernel(int* __restrict__ cnt, const int* __restrict__ boff,
                                  int* __restrict__ rowptr, int* __restrict__ fill,
                                  float* __restrict__ invdeg, int n) {
    __shared__ int wsum[8];
    int i = blockIdx.x * 256 + threadIdx.x;
    int lane = threadIdx.x & 31, wid = threadIdx.x >> 5;
    int v = (i < n) ? cnt[i] : 0;
    int s = v;
#pragma unroll
    for (int off = 1; off < 32; off <<= 1) {
        int u = __shfl_up_sync(0xffffffffu, s, off);
        if (lane >= off) s += u;
    }
    if (lane == 31) wsum[wid] = s;
    __syncthreads();
    if (wid == 0 && lane < 8) {
        int w = wsum[lane];
#pragma unroll
        for (int off = 1; off < 8; off <<= 1) {
            int u = __shfl_up_sync(0xffu, w, off);
            if (lane >= off) w += u;
        }
        wsum[lane] = w;
    }
    __syncthreads();
    int incl = s + (wid ? wsum[wid - 1] : 0) + boff[blockIdx.x];
    if (i < n) {
        rowptr[i + 1] = incl;
        fill[i] = incl - v;
        invdeg[i] = 1.0f / (float)(v > 0 ? v : 1);
        cnt[i] = 0;
    }
    if (i == 0) rowptr[0] = 0;
}

__global__ void scatter_kernel(const int* __restrict__ ei, int ne,
                               int* __restrict__ fill, int* __restrict__ csr) {
    int e = blockIdx.x * blockDim.x + threadIdx.x;
    if (e < ne) {
        int s = ei[e];
        int d = ei[ne + e];
        if ((unsigned)d < (unsigned)NNODES && (unsigned)s < (unsigned)NNODES) {
            int pos = atomicAdd(&fill[d], 1);
            if ((unsigned)pos < (unsigned)NEDGES)
                csr[pos] = s;
        }
    }
}

// ------------------------- fused prologue kernel -----------------------------
__global__ void prologue_kernel(const float* __restrict__ Wl0, const float* __restrict__ Wr0,
                                const float* __restrict__ Wl1, const float* __restrict__ Wr1,
                                const float* __restrict__ Wl2, const float* __restrict__ Wr2,
                                __half* __restrict__ wl0t, __half* __restrict__ wr0t,
                                __half* __restrict__ wl1t, __half* __restrict__ wr1t,
                                __half* __restrict__ wcatt,
                                const float4* __restrict__ x4, __half2* __restrict__ xh2) {
    int i = blockIdx.x * blockDim.x + threadIdx.x;
    if (i < WSEG) {
        if (i < 65536) {
            int j = i & 32767;
            int n = j >> 7, k = j & 127;
            const float* W = (i < 32768) ? Wl0 : Wr0;
            __half* Wt = (i < 32768) ? wl0t : wr0t;
            Wt[j] = __float2half_rn(W[k * HIDDIM + n]);
        } else if (i < 196608) {
            int j = (i - 65536) & 65535;
            int n = j >> 8, k = j & 255;
            const float* W = (i < 131072) ? Wl1 : Wr1;
            __half* Wt = (i < 131072) ? wl1t : wr1t;
            Wt[j] = __float2half_rn(W[k * HIDDIM + n]);
        } else {
            int j = i - 196608;
            int n = j >> 8, k = j & 255;
            float v = (n < 64) ? Wl2[k * 64 + n] : Wr2[k * 64 + (n - 64)];
            wcatt[j] = __float2half_rn(v);
        }
    } else {
        int j = i - WSEG;
        if (j < XSEG) {
            float4 v = x4[j];
            xh2[j * 2 + 0] = __floats2half2_rn(v.x, v.y);
            xh2[j * 2 + 1] = __floats2half2_rn(v.z, v.w);
        }
    }
}

// ------------------ act (BN+ReLU) -> fp16 (gather + GEMM A) ------------------
__global__ void act_f16_kernel(const float4* __restrict__ H, __half2* __restrict__ O2,
                               int n4, const float* __restrict__ sc, const float* __restrict__ sh) {
    int i = blockIdx.x * blockDim.x + threadIdx.x;
    if (i >= n4) return;
    int c = (i * 4) & (HIDDIM - 1);
    float4 v = H[i];
    v.x = fmaxf(v.x * __ldg(sc + c + 0) + __ldg(sh + c + 0), 0.f);
    v.y = fmaxf(v.y * __ldg(sc + c + 1) + __ldg(sh + c + 1), 0.f);
    v.z = fmaxf(v.z * __ldg(sc + c + 2) + __ldg(sh + c + 2), 0.f);
    v.w = fmaxf(v.w * __ldg(sc + c + 3) + __ldg(sh + c + 3), 0.f);
    O2[i * 2 + 0] = __floats2half2_rn(v.x, v.y);
    O2[i * 2 + 1] = __floats2half2_rn(v.z, v.w);
}

// ------------------------- fp16 aggregation (D=256) --------------------------
// 8-edge main loop (MLP 8); bank assignment matches R15 -> identical order.
__global__ void agg256_f16_kernel(const __half* __restrict__ Xh, __half* __restrict__ Out,
                                  const int* __restrict__ rowptr, const int* __restrict__ csr,
                                  const float* __restrict__ invdeg, int n_nodes) {
    int node = (blockIdx.x * blockDim.x + threadIdx.x) >> 5;
    if (node >= n_nodes) return;
    int lane = threadIdx.x & 31;
    int doff = lane * 8;

    float acc0[8], acc1[8];
#pragma unroll
    for (int i = 0; i < 8; i++) { acc0[i] = 0.f; acc1[i] = 0.f; }

    int beg = rowptr[node];
    int end = rowptr[node + 1];
    int e = beg;

    auto accum = [&](uint4 u, float* acc) {
        float2 f0 = __half22float2(*reinterpret_cast<__half2*>(&u.x));
        float2 f1 = __half22float2(*reinterpret_cast<__half2*>(&u.y));
        float2 f2 = __half22float2(*reinterpret_cast<__half2*>(&u.z));
        float2 f3 = __half22float2(*reinterpret_cast<__half2*>(&u.w));
        acc[0] += f0.x; acc[1] += f0.y;
        acc[2] += f1.x; acc[3] += f1.y;
        acc[4] += f2.x; acc[5] += f2.y;
        acc[6] += f3.x; acc[7] += f3.y;
    };

    for (; e + 7 < end; e += 8) {
        int s0 = __ldg(csr + e);
        int s1 = __ldg(csr + e + 1);
        int s2 = __ldg(csr + e + 2);
        int s3 = __ldg(csr + e + 3);
        int s4 = __ldg(csr + e + 4);
        int s5 = __ldg(csr + e + 5);
        int s6 = __ldg(csr + e + 6);
        int s7 = __ldg(csr + e + 7);
        uint4 u0 = __ldg(reinterpret_cast<const uint4*>(Xh + (size_t)s0 * HIDDIM + doff));
        uint4 u1 = __ldg(reinterpret_cast<const uint4*>(Xh + (size_t)s1 * HIDDIM + doff));
        uint4 u2 = __ldg(reinterpret_cast<const uint4*>(Xh + (size_t)s2 * HIDDIM + doff));
        uint4 u3 = __ldg(reinterpret_cast<const uint4*>(Xh + (size_t)s3 * HIDDIM + doff));
        uint4 u4 = __ldg(reinterpret_cast<const uint4*>(Xh + (size_t)s4 * HIDDIM + doff));
        uint4 u5 = __ldg(reinterpret_cast<const uint4*>(Xh + (size_t)s5 * HIDDIM + doff));
        uint4 u6 = __ldg(reinterpret_cast<const uint4*>(Xh + (size_t)s6 * HIDDIM + doff));
        uint4 u7 = __ldg(reinterpret_cast<const uint4*>(Xh + (size_t)s7 * HIDDIM + doff));
        accum(u0, acc0); accum(u1, acc1); accum(u2, acc0); accum(u3, acc1);
        accum(u4, acc0); accum(u5, acc1); accum(u6, acc0); accum(u7, acc1);
    }
    if (e + 3 < end) {
        int s0 = __ldg(csr + e);
        int s1 = __ldg(csr + e + 1);
        int s2 = __ldg(csr + e + 2);
        int s3 = __ldg(csr + e + 3);
        uint4 u0 = __ldg(reinterpret_cast<const uint4*>(Xh + (size_t)s0 * HIDDIM + doff));
        uint4 u1 = __ldg(reinterpret_cast<const uint4*>(Xh + (size_t)s1 * HIDDIM + doff));
        uint4 u2 = __ldg(reinterpret_cast<const uint4*>(Xh + (size_t)s2 * HIDDIM + doff));
        uint4 u3 = __ldg(reinterpret_cast<const uint4*>(Xh + (size_t)s3 * HIDDIM + doff));
        accum(u0, acc0); accum(u1, acc1); accum(u2, acc0); accum(u3, acc1);
        e += 4;
    }
    for (; e < end; e++) {
        int s0 = __ldg(csr + e);
        uint4 u0 = __ldg(reinterpret_cast<const uint4*>(Xh + (size_t)s0 * HIDDIM + doff));
        accum(u0, acc0);
    }

    float w = __ldg(invdeg + node);
    uint4 ov;
    __half2 h0 = __floats2half2_rn((acc0[0] + acc1[0]) * w, (acc0[1] + acc1[1]) * w);
    __half2 h1v = __floats2half2_rn((acc0[2] + acc1[2]) * w, (acc0[3] + acc1[3]) * w);
    __half2 h2v = __floats2half2_rn((acc0[4] + acc1[4]) * w, (acc0[5] + acc1[5]) * w);
    __half2 h3 = __floats2half2_rn((acc0[6] + acc1[6]) * w, (acc0[7] + acc1[7]) * w);
    ov.x = *reinterpret_cast<uint32_t*>(&h0);
    ov.y = *reinterpret_cast<uint32_t*>(&h1v);
    ov.z = *reinterpret_cast<uint32_t*>(&h2v);
    ov.w = *reinterpret_cast<uint32_t*>(&h3);
    *reinterpret_cast<uint4*>(Out + (size_t)node * HIDDIM + doff) = ov;
}

// ------------------------- fp16 aggregation (D=128) --------------------------
__global__ void agg128_f16_kernel(const __half* __restrict__ Xh, __half* __restrict__ Out,
                                  const int* __restrict__ rowptr, const int* __restrict__ csr,
                                  const float* __restrict__ invdeg, int n_nodes) {
    int node = (blockIdx.x * blockDim.x + threadIdx.x) >> 5;
    if (node >= n_nodes) return;
    int lane = threadIdx.x & 31;
    int doff = lane * 4;

    float acc0[4], acc1[4];
#pragma unroll
    for (int i = 0; i < 4; i++) { acc0[i] = 0.f; acc1[i] = 0.f; }

    int beg = rowptr[node];
    int end = rowptr[node + 1];
    int e = beg;

    auto accum = [&](uint2 u, float* acc) {
        float2 f0 = __half22float2(*reinterpret_cast<__half2*>(&u.x));
        float2 f1 = __half22float2(*reinterpret_cast<__half2*>(&u.y));
        acc[0] += f0.x; acc[1] += f0.y;
        acc[2] += f1.x; acc[3] += f1.y;
    };

    for (; e + 7 < end; e += 8) {
        int s0 = __ldg(csr + e);
        int s1 = __ldg(csr + e + 1);
        int s2 = __ldg(csr + e + 2);
        int s3 = __ldg(csr + e + 3);
        int s4 = __ldg(csr + e + 4);
        int s5 = __ldg(csr + e + 5);
        int s6 = __ldg(csr + e + 6);
        int s7 = __ldg(csr + e + 7);
        uint2 u0 = __ldg(reinterpret_cast<const uint2*>(Xh + (size_t)s0 * INDIM + doff));
        uint2 u1 = __ldg(reinterpret_cast<const uint2*>(Xh + (size_t)s1 * INDIM + doff));
        uint2 u2 = __ldg(reinterpret_cast<const uint2*>(Xh + (size_t)s2 * INDIM + doff));
        uint2 u3 = __ldg(reinterpret_cast<const uint2*>(Xh + (size_t)s3 * INDIM + doff));
        uint2 u4 = __ldg(reinterpret_cast<const uint2*>(Xh + (size_t)s4 * INDIM + doff));
        uint2 u5 = __ldg(reinterpret_cast<const uint2*>(Xh + (size_t)s5 * INDIM + doff));
        uint2 u6 = __ldg(reinterpret_cast<const uint2*>(Xh + (size_t)s6 * INDIM + doff));
        uint2 u7 = __ldg(reinterpret_cast<const uint2*>(Xh + (size_t)s7 * INDIM + doff));
        accum(u0, acc0); accum(u1, acc1); accum(u2, acc0); accum(u3, acc1);
        accum(u4, acc0); accum(u5, acc1); accum(u6, acc0); accum(u7, acc1);
    }
    if (e + 3 < end) {
        int s0 = __ldg(csr + e);
        int s1 = __ldg(csr + e + 1);
        int s2 = __ldg(csr + e + 2);
        int s3 = __ldg(csr + e + 3);
        uint2 u0 = __ldg(reinterpret_cast<const uint2*>(Xh + (size_t)s0 * INDIM + doff));
        uint2 u1 = __ldg(reinterpret_cast<const uint2*>(Xh + (size_t)s1 * INDIM + doff));
        uint2 u2 = __ldg(reinterpret_cast<const uint2*>(Xh + (size_t)s2 * INDIM + doff));
        uint2 u3 = __ldg(reinterpret_cast<const uint2*>(Xh + (size_t)s3 * INDIM + doff));
        accum(u0, acc0); accum(u1, acc1); accum(u2, acc0); accum(u3, acc1);
        e += 4;
    }
    for (; e < end; e++) {
        int s0 = __ldg(csr + e);
        uint2 u0 = __ldg(reinterpret_cast<const uint2*>(Xh + (size_t)s0 * INDIM + doff));
        accum(u0, acc0);
    }

    float w = __ldg(invdeg + node);
    __half2 h0 = __floats2half2_rn((acc0[0] + acc1[0]) * w, (acc0[1] + acc1[1]) * w);
    __half2 h1v = __floats2half2_rn((acc0[2] + acc1[2]) * w, (acc0[3] + acc1[3]) * w);
    uint2 ov;
    ov.x = *reinterpret_cast<uint32_t*>(&h0);
    ov.y = *reinterpret_cast<uint32_t*>(&h1v);
    *reinterpret_cast<uint2*>(Out + (size_t)node * INDIM + doff) = ov;
}

// ------------------------- fp16 aggregation (D=64, ADD) ----------------------
__global__ void agg64_f16_kernel(const __half* __restrict__ Yh, float* __restrict__ Out,
                                 const int* __restrict__ rowptr, const int* __restrict__ csr,
                                 const float* __restrict__ invdeg, int n_nodes) {
    int node = (blockIdx.x * blockDim.x + threadIdx.x) >> 5;
    if (node >= n_nodes) return;
    int lane = threadIdx.x & 31;
    int doff = lane * 2;

    float a0 = 0.f, a1 = 0.f, b0 = 0.f, b1 = 0.f;

    int beg = rowptr[node];
    int end = rowptr[node + 1];
    int e = beg;

    for (; e + 3 < end; e += 4) {
        int s0 = __ldg(csr + e);
        int s1 = __ldg(csr + e + 1);
        int s2 = __ldg(csr + e + 2);
        int s3 = __ldg(csr + e + 3);
        float2 f0 = __half22float2(*reinterpret_cast<const __half2*>(Yh + (size_t)s0 * OUTDIM + doff));
        float2 f1 = __half22float2(*reinterpret_cast<const __half2*>(Yh + (size_t)s1 * OUTDIM + doff));
        float2 f2 = __half22float2(*reinterpret_cast<const __half2*>(Yh + (size_t)s2 * OUTDIM + doff));
        float2 f3 = __half22float2(*reinterpret_cast<const __half2*>(Yh + (size_t)s3 * OUTDIM + doff));
        a0 += f0.x + f2.x;  b0 += f1.x + f3.x;
        a1 += f0.y + f2.y;  b1 += f1.y + f3.y;
    }
    for (; e < end; e++) {
        int s0 = __ldg(csr + e);
        float2 f0 = __half22float2(*reinterpret_cast<const __half2*>(Yh + (size_t)s0 * OUTDIM + doff));
        a0 += f0.x; a1 += f0.y;
    }

    float w = __ldg(invdeg + node);
    float* o = Out + (size_t)node * OUTDIM + doff;
    o[0] += (a0 + b0) * w;
    o[1] += (a1 + b1) * w;
}

// ------------------------------ FP16 GEMM (R12) ------------------------------
__device__ __forceinline__ void mma_f16(float c[4], const unsigned a[4], const unsigned b[2]) {
    asm volatile(
        "mma.sync.aligned.m16n8k16.row.col.f32.f16.f16.f32 "
        "{%0,%1,%2,%3}, {%4,%5,%6,%7}, {%8,%9}, {%0,%1,%2,%3};"
        : "+f"(c[0]), "+f"(c[1]), "+f"(c[2]), "+f"(c[3])
        : "r"(a[0]), "r"(a[1]), "r"(a[2]), "r"(a[3]), "r"(b[0]), "r"(b[1]));
}

template <int BM, int BN, int WM, int WN>
__global__ void __launch_bounds__(256, 2)
gemm_f16(const __half* __restrict__ A0, const __half* __restrict__ B0t,
         const __half* __restrict__ A1, const __half* __restrict__ B1t,
         float* __restrict__ C, __half* __restrict__ Cy,
         int M, int N, int K, const float* __restrict__ bias,
         float* __restrict__ Sp, float* __restrict__ Sq) {
    constexpr int BK = 32, THREADS = 256;
    constexpr int WCOLS = BN / WN;
    constexpr int MT = WM / 16, NT = WN / 8;
    constexpr int AST = BK + 8;
    constexpr int BST = BK + 8;
    constexpr int ACH = (BM * BK) / (8 * THREADS);
    constexpr int BCH = (BN * BK) / (8 * THREADS);
    constexpr int ABUF = BM * AST;
    constexpr int BBUF = BN * BST;
    static_assert((BM / WM) * (BN / WN) == 8, "8 warps");

    __shared__ __half Asm[2 * ABUF];
    __shared__ __half Bsm[2 * BBUF];
    __shared__ float sstat[2][2][BN];

    int tid = threadIdx.x, lane = tid & 31, warp = tid >> 5;
    int wrow = warp / WCOLS, wcol = warp % WCOLS;
    int block_m = blockIdx.y * BM, block_n = blockIdx.x * BN;
    int g = lane >> 2, q = lane & 3;

    uint32_t AsmAddr = (uint32_t)__cvta_generic_to_shared(Asm);
    uint32_t BsmAddr = (uint32_t)__cvta_generic_to_shared(Bsm);

    float acc[MT][NT][4];
#pragma unroll
    for (int mt = 0; mt < MT; mt++)
#pragma unroll
        for (int nt = 0; nt < NT; nt++)
#pragma unroll
            for (int r = 0; r < 4; r++) acc[mt][nt][r] = 0.0f;

    const int kiters = K / BK;
    const int npass = A1 ? 2 : 1;
    const int total = npass * kiters;

    auto issue_stage = [&](int it, int buf) {
        int pass = it / kiters;
        int k0 = (it - pass * kiters) * BK;
        const __half* Ap = pass ? A1 : A0;
        const __half* Bp = pass ? B1t : B0t;
#pragma unroll
        for (int i = 0; i < ACH; i++) {
            int chunk = tid + i * THREADS;
            int r = chunk >> 2;
            int c8 = (chunk & 3) << 3;
            int gr = block_m + r;
            uint32_t dst = AsmAddr + (buf * ABUF + r * AST + c8) * 2;
            cp_async16(dst, Ap + (size_t)gr * K + k0 + c8, gr < M);
        }
#pragma unroll
        for (int i = 0; i < BCH; i++) {
            int chunk = tid + i * THREADS;
            int r = chunk >> 2;
            int c8 = (chunk & 3) << 3;
            uint32_t dst = BsmAddr + (buf * BBUF + r * BST + c8) * 2;
            cp_async16(dst, Bp + (size_t)(block_n + r) * K + k0 + c8, true);
        }
        cp_commit();
    };

    issue_stage(0, 0);
    int buf = 0;
    for (int it = 0; it < total; ++it) {
        cp_wait0();
        __syncthreads();
        if (it + 1 < total) issue_stage(it + 1, buf ^ 1);

        const __half* Ab = Asm + buf * ABUF;
        const __half* Bb = Bsm + buf * BBUF;
#pragma unroll
        for (int s = 0; s < BK / 16; ++s) {
            int kb = s * 16 + q * 2;
            unsigned af[MT][4], bf[NT][2];
#pragma unroll
            for (int mt = 0; mt < MT; ++mt) {
                int m = wrow * WM + mt * 16 + g;
                af[mt][0] = *reinterpret_cast<const unsigned*>(Ab + m * AST + kb);
                af[mt][1] = *reinterpret_cast<const unsigned*>(Ab + (m + 8) * AST + kb);
                af[mt][2] = *reinterpret_cast<const unsigned*>(Ab + m * AST + kb + 8);
                af[mt][3] = *reinterpret_cast<const unsigned*>(Ab + (m + 8) * AST + kb + 8);
            }
#pragma unroll
            for (int nt = 0; nt < NT; ++nt) {
                int nn = wcol * WN + nt * 8 + g;
                bf[nt][0] = *reinterpret_cast<const unsigned*>(Bb + nn * BST + kb);
                bf[nt][1] = *reinterpret_cast<const unsigned*>(Bb + nn * BST + kb + 8);
            }
#pragma unroll
            for (int mt = 0; mt < MT; ++mt)
#pragma unroll
                for (int nt = 0; nt < NT; ++nt)
                    mma_f16(acc[mt][nt], af[mt], bf[nt]);
        }
        buf ^= 1;
    }

    float csum[NT][2], csq[NT][2];
#pragma unroll
    for (int nt = 0; nt < NT; nt++) {
        csum[nt][0] = csum[nt][1] = 0.f;
        csq[nt][0]  = csq[nt][1]  = 0.f;
    }

#pragma unroll
    for (int mt = 0; mt < MT; ++mt) {
        int r0 = block_m + wrow * WM + mt * 16 + g;
        int r1 = r0 + 8;
#pragma unroll
        for (int nt = 0; nt < NT; ++nt) {
            int cn = block_n + wcol * WN + nt * 8 + q * 2;
            if (Cy) {
                if (cn < 64) {
                    if (r0 < M)
                        *reinterpret_cast<__half2*>(Cy + (size_t)r0 * 64 + cn) =
                            __floats2half2_rn(acc[mt][nt][0], acc[mt][nt][1]);
                    if (r1 < M)
                        *reinterpret_cast<__half2*>(Cy + (size_t)r1 * 64 + cn) =
                            __floats2half2_rn(acc[mt][nt][2], acc[mt][nt][3]);
                } else {
                    int co = cn - 64;
                    float b0 = __ldg(bias + co), b1 = __ldg(bias + co + 1);
                    if (r0 < M) {
                        float2 t0 = make_float2(acc[mt][nt][0] + b0, acc[mt][nt][1] + b1);
                        *reinterpret_cast<float2*>(C + (size_t)r0 * 64 + co) = t0;
                    }
                    if (r1 < M) {
                        float2 t1 = make_float2(acc[mt][nt][2] + b0, acc[mt][nt][3] + b1);
                        *reinterpret_cast<float2*>(C + (size_t)r1 * 64 + co) = t1;
                    }
                }
            } else {
                float b0 = 0.f, b1 = 0.f;
                if (bias) { b0 = __ldg(bias + cn); b1 = __ldg(bias + cn + 1); }
                if (r0 < M) {
                    float2 t0 = make_float2(acc[mt][nt][0] + b0, acc[mt][nt][1] + b1);
                    *reinterpret_cast<float2*>(C + (size_t)r0 * N + cn) = t0;
                    if (Sp) {
                        csum[nt][0] += t0.x;        csum[nt][1] += t0.y;
                        csq[nt][0]  += t0.x * t0.x; csq[nt][1]  += t0.y * t0.y;
                    }
                }
                if (r1 < M) {
                    float2 t1 = make_float2(acc[mt][nt][2] + b0, acc[mt][nt][3] + b1);
                    *reinterpret_cast<float2*>(C + (size_t)r1 * N + cn) = t1;
                    if (Sp) {
                        csum[nt][0] += t1.x;        csum[nt][1] += t1.y;
                        csq[nt][0]  += t1.x * t1.x; csq[nt][1]  += t1.y * t1.y;
                    }
                }
            }
        }
    }

    if (Sp) {
#pragma unroll
        for (int nt = 0; nt < NT; nt++)
#pragma unroll
            for (int c = 0; c < 2; c++) {
                float s = csum[nt][c], sq = csq[nt][c];
#pragma unroll
                for (int off = 16; off >= 4; off >>= 1) {
                    s  += __shfl_down_sync(0xffffffffu, s,  off);
                    sq += __shfl_down_sync(0xffffffffu, sq, off);
                }
                if (lane < 4) {
                    int col = wcol * WN + nt * 8 + lane * 2 + c;
                    sstat[wrow][0][col] = s;
                    sstat[wrow][1][col] = sq;
                }
            }
        __syncthreads();
        if (tid < BN) {
            size_t o = (size_t)blockIdx.y * N + block_n + tid;
            Sp[o] = sstat[0][0][tid] + sstat[1][0][tid];
            Sq[o] = sstat[0][1][tid] + sstat[1][1][tid];
        }
    }
}

// ------------------------------- BatchNorm ----------------------------------
__global__ void colstats_final(const float* __restrict__ ps, const float* __restrict__ pq,
                               int nb, float inv_m,
                               const float* __restrict__ g, const float* __restrict__ be,
                               float* __restrict__ scale, float* __restrict__ shift) {
    int c = threadIdx.x;
    float s = 0.f, q = 0.f;
    for (int b = 0; b < nb; b++) {
        s += ps[b * HIDDIM + c];
        q += pq[b * HIDDIM + c];
    }
    float mu  = s * inv_m;
    float var = q * inv_m - mu * mu;
    float rs  = rsqrtf(var + 1e-5f);
    float sc  = g[c] * rs;
    scale[c] = sc;
    shift[c] = be[c] - mu * sc;
}

// --------------------------------- launch -----------------------------------
extern "C" void kernel_launch(void* const* d_in, const int* in_sizes, int n_in,
                              void* d_out, int out_size) {
    const float* x   = (const float*)d_in[0];
    const int*   ei  = (const int*)d_in[1];
    const float* Wl0 = (const float*)d_in[2];
    const float* bl0 = (const float*)d_in[3];
    const float* Wr0 = (const float*)d_in[4];
    const float* Wl1 = (const float*)d_in[5];
    const float* bl1 = (const float*)d_in[6];
    const float* Wr1 = (const float*)d_in[7];
    const float* Wl2 = (const float*)d_in[8];
    const float* bl2 = (const float*)d_in[9];
    const float* Wr2 = (const float*)d_in[10];
    const float* g0  = (const float*)d_in[11];
    const float* be0 = (const float*)d_in[12];
    const float* g1  = (const float*)d_in[13];
    const float* be1 = (const float*)d_in[14];
    float* out = (float*)d_out;

    const int N  = NNODES;
    const int NE = NEDGES;

    float *h1, *h2, *invdeg, *ps, *pq, *scale, *shift;
    __half *aggh, *xh, *h1h, *h2h, *yh, *wl0t, *wr0t, *wl1t, *wr1t, *wcatt;
    int *cnt, *rowptr, *fill, *csr, *bsum;
    cudaGetSymbolAddress((void**)&h1,     g_h1);
    cudaGetSymbolAddress((void**)&h2,     g_h2);
    cudaGetSymbolAddress((void**)&aggh,   g_aggh);
    cudaGetSymbolAddress((void**)&xh,     g_xh);
    cudaGetSymbolAddress((void**)&h1h,    g_h1h);
    cudaGetSymbolAddress((void**)&h2h,    g_h2h);
    cudaGetSymbolAddress((void**)&yh,     g_yh);
    cudaGetSymbolAddress((void**)&wl0t,   g_wl0t);
    cudaGetSymbolAddress((void**)&wr0t,   g_wr0t);
    cudaGetSymbolAddress((void**)&wl1t,   g_wl1t);
    cudaGetSymbolAddress((void**)&wr1t,   g_wr1t);
    cudaGetSymbolAddress((void**)&wcatt,  g_wcatt);
    cudaGetSymbolAddress((void**)&invdeg, g_invdeg);
    cudaGetSymbolAddress((void**)&cnt,    g_cnt);
    cudaGetSymbolAddress((void**)&rowptr, g_rowptr);
    cudaGetSymbolAddress((void**)&fill,   g_fill);
    cudaGetSymbolAddress((void**)&csr,    g_csr);
    cudaGetSymbolAddress((void**)&bsum,   g_bsum);
    cudaGetSymbolAddress((void**)&ps,     g_ps);
    cudaGetSymbolAddress((void**)&pq,     g_pq);
    cudaGetSymbolAddress((void**)&scale,  g_scale);
    cudaGetSymbolAddress((void**)&shift,  g_shift);

    dim3 gridBig(HIDDIM / 128, (N + 127) / 128);
    dim3 gridL2(1, (N + 127) / 128);
    const int AGG_BLOCKS = (N + 7) / 8;

    // ---- CSR build (cnt self-zeroing) + fused prologue ----
    hist_kernel<<<(NE + 255) / 256, 256>>>(ei, NE, cnt);
    scan_bsums_kernel<<<NBLK, 256>>>(cnt, bsum, N);
    scan_offsets_kernel<<<1, 256>>>(bsum, NBLK);
    scan_final_kernel<<<NBLK, 256>>>(cnt, bsum, rowptr, fill, invdeg, N);
    scatter_kernel<<<(NE + 255) / 256, 256>>>(ei, NE, fill, csr);
    prologue_kernel<<<(WSEG + XSEG + 255) / 256, 256>>>(
        Wl0, Wr0, Wl1, Wr1, Wl2, Wr2,
        wl0t, wr0t, wl1t, wr1t, wcatt,
        (const float4*)x, (__half2*)xh);

    // ---- Layer 0: h1 = mean_agg(x) @ Wl0 + x @ Wr0 + bl0  (+ fused stats) ----
    agg128_f16_kernel<<<AGG_BLOCKS, 256>>>(xh, aggh, rowptr, csr, invdeg, N);
    gemm_f16<128, 128, 64, 32><<<gridBig, 256>>>(
        aggh, wl0t, xh, wr0t, h1, nullptr, N, HIDDIM, INDIM, bl0, ps, pq);
    colstats_final<<<1, HIDDIM>>>(ps, pq, NBY, 1.0f / (float)N, g0, be0, scale, shift);

    // ---- Layer 1: h2 = mean_agg(act0(h1)) @ Wl1 + act0(h1) @ Wr1 + bl1 ----
    act_f16_kernel<<<(N * HIDDIM / 4 + 255) / 256, 256>>>(
        (const float4*)h1, (__half2*)h1h, N * HIDDIM / 4, scale, shift);
    agg256_f16_kernel<<<AGG_BLOCKS, 256>>>(h1h, aggh, rowptr, csr, invdeg, N);
    gemm_f16<128, 128, 64, 32><<<gridBig, 256>>>(
        aggh, wl1t, h1h, wr1t, h2, nullptr, N, HIDDIM, HIDDIM, bl1, ps, pq);
    colstats_final<<<1, HIDDIM>>>(ps, pq, NBY, 1.0f / (float)N, g1, be1, scale, shift);

    // ---- Layer 2 (fused): [y | out] = act1(h2) @ [Wl2 | Wr2]; y fp16 ----
    act_f16_kernel<<<(N * HIDDIM / 4 + 255) / 256, 256>>>(
        (const float4*)h2, (__half2*)h2h, N * HIDDIM / 4, scale, shift);
    gemm_f16<128, 128, 64, 32><<<gridL2, 256>>>(
        h2h, wcatt, nullptr, nullptr, out, yh, N, 128, HIDDIM, bl2, nullptr, nullptr);
    agg64_f16_kernel<<<AGG_BLOCKS, 256>>>(yh, out, rowptr, csr, invdeg, N);
}